// round 1
// baseline (speedup 1.0000x reference)
#include <cuda_runtime.h>
#include <math.h>

// ---------------------------------------------------------------------------
// GCN_13821204759316: per-batch graph conv (GEMM) + 3x3 conv + BN(train) + ReLU
// b=8, c=256, h=w=32, n=1024. All fp32.
//
// out_inter[b,c,i] = d[i]*( sum_j (d[j]*x[b,c,j]) * ind[b,j,i] ) + d[i]^2 * x[b,c,i]
//   with d[b,i] = rsqrt( sum_j ind[b,j,i] + 1e-8 )
// y = conv3x3(out_inter, W) + bias ; out = relu(BN_train(y)*gamma + beta)
// ---------------------------------------------------------------------------

#define BATCH 8
#define C     256
#define N     1024   // h*w
#define HW    32
#define CN    (C*N)        // 262144
#define NN    (N*N)        // 1048576

// scratch (device globals; allocation is forbidden)
__device__ float g_part[BATCH * 16 * N];   // partial column sums
__device__ float g_d[BATCH * N];           // d[b,i]
__device__ float g_xt[BATCH * CN];         // Xs transposed: [b][j][c] = x[b][c][j]*d[b][j]
__device__ float g_inter[BATCH * CN];      // out_inter [b][c][n]
__device__ float g_y[BATCH * CN];          // conv output [b][c][n]
__device__ float g_wr[9 * C * C];          // weights re-laid: [tap][ci][co]
__device__ float g_scale[C], g_shift[C];   // BN fold

// ---------------- degree: partial column sums of ind ----------------
__global__ void deg_part_kernel(const float* __restrict__ ind) {
    int b  = blockIdx.z;
    int jc = blockIdx.y;                       // 16 j-chunks of 64
    int i  = blockIdx.x * 256 + threadIdx.x;   // 0..1023
    const float* p = ind + (size_t)b * NN + (size_t)(jc * 64) * N + i;
    float s = 0.f;
    #pragma unroll 8
    for (int jj = 0; jj < 64; ++jj) s += p[jj * N];
    g_part[(b * 16 + jc) * N + i] = s;
}

__global__ void deg_final_kernel() {
    int gi = blockIdx.x * 256 + threadIdx.x;   // 0..8191
    int b = gi >> 10, i = gi & (N - 1);
    float s = 0.f;
    #pragma unroll
    for (int jc = 0; jc < 16; ++jc) s += g_part[(b * 16 + jc) * N + i];
    g_d[b * N + i] = sqrtf(1.0f / (s + 1e-8f));
}

// ---------------- transpose + scale: g_xt[b][j][c] = x[b][c][j]*d[b][j] -----
__global__ void xt_kernel(const float* __restrict__ x) {
    __shared__ float tile[32][33];
    int b  = blockIdx.z;
    int j0 = blockIdx.x * 32;
    int c0 = blockIdx.y * 32;
    int tx = threadIdx.x, ty = threadIdx.y;    // block (32,8)
    #pragma unroll
    for (int r = 0; r < 4; ++r) {
        int row = ty + r * 8;                  // c offset
        tile[row][tx] = x[(size_t)b * CN + (size_t)(c0 + row) * N + j0 + tx];
    }
    __syncthreads();
    #pragma unroll
    for (int r = 0; r < 4; ++r) {
        int row = ty + r * 8;                  // j offset
        float dj = g_d[b * N + j0 + row];
        g_xt[(size_t)b * CN + (size_t)(j0 + row) * C + c0 + tx] = tile[tx][row] * dj;
    }
}

// ---------------- weight relayout: g_wr[tap][ci][co] = w[co][ci][tap] -------
__global__ void wtr_kernel(const float* __restrict__ w) {
    int idx = blockIdx.x * 256 + threadIdx.x;
    if (idx >= 9 * C * C) return;
    int co  = idx / (C * 9);
    int rem = idx - co * (C * 9);
    int ci  = rem / 9;
    int tap = rem - ci * 9;
    g_wr[tap * (C * C) + ci * C + co] = w[idx];
}

// ---------------- GEMM: T = Xs @ ind ; inter = d*T + d^2*x ------------------
// tiles: BM=64 (c), BN=64 (i), BK=16 (j). 256 threads, 4x4 micro-tile.
__global__ void gcn_gemm_kernel(const float* __restrict__ ind,
                                const float* __restrict__ x) {
    int b  = blockIdx.z;
    int n0 = blockIdx.x * 64;
    int m0 = blockIdx.y * 64;
    const float* Xt = g_xt + (size_t)b * CN;        // [j][c]
    const float* Bm = ind + (size_t)b * NN;         // [j][i]

    __shared__ float As[16][64];  // [k][m]
    __shared__ float Bs[16][64];  // [k][n]

    int t = threadIdx.x;
    int tx = t & 15, ty = t >> 4;                   // 16x16
    int lrow = t >> 6, lcol = t & 63;               // loader: 4 rows x 64 cols

    float acc[4][4] = {};

    for (int k0 = 0; k0 < N; k0 += 16) {
        #pragma unroll
        for (int rr = 0; rr < 4; ++rr) {
            int k = lrow + rr * 4;
            As[k][lcol] = Xt[(size_t)(k0 + k) * C + m0 + lcol];
            Bs[k][lcol] = Bm[(size_t)(k0 + k) * N + n0 + lcol];
        }
        __syncthreads();
        #pragma unroll
        for (int k = 0; k < 16; ++k) {
            float a[4], bb[4];
            #pragma unroll
            for (int e = 0; e < 4; ++e) a[e]  = As[k][ty * 4 + e];
            #pragma unroll
            for (int e = 0; e < 4; ++e) bb[e] = Bs[k][tx * 4 + e];
            #pragma unroll
            for (int i = 0; i < 4; ++i)
                #pragma unroll
                for (int j = 0; j < 4; ++j)
                    acc[i][j] = fmaf(a[i], bb[j], acc[i][j]);
        }
        __syncthreads();
    }

    #pragma unroll
    for (int i = 0; i < 4; ++i) {
        int c = m0 + ty * 4 + i;
        #pragma unroll
        for (int j = 0; j < 4; ++j) {
            int col = n0 + tx * 4 + j;
            float di = g_d[b * N + col];
            float xv = x[(size_t)b * CN + (size_t)c * N + col];
            g_inter[(size_t)b * CN + (size_t)c * N + col] =
                di * acc[i][j] + di * di * xv;
        }
    }
}

// ---------------- conv 3x3 as implicit GEMM over 9 taps ---------------------
__global__ void gcn_conv_kernel(const float* __restrict__ conv_b) {
    int b   = blockIdx.z;
    int co0 = blockIdx.y * 64;
    int p0  = blockIdx.x * 64;

    __shared__ float Ws[16][64];  // [ci_k][co]
    __shared__ float Xs[16][64];  // [ci_k][pos]

    int t = threadIdx.x;
    int tx = t & 15, ty = t >> 4;
    int lrow = t >> 6, lcol = t & 63;

    // per-loader-column spatial position
    int pos = p0 + lcol;
    int ph = pos >> 5, pw = pos & 31;

    float acc[4][4] = {};

    for (int tap = 0; tap < 9; ++tap) {
        int dh = tap / 3 - 1, dw = tap % 3 - 1;
        int sh = ph + dh, sw = pw + dw;
        bool valid = ((unsigned)sh < HW) && ((unsigned)sw < HW);
        int sidx = (sh << 5) + sw;
        const float* wr = g_wr + tap * (C * C);

        for (int kc = 0; kc < 16; ++kc) {
            int ci0 = kc * 16;
            #pragma unroll
            for (int rr = 0; rr < 4; ++rr) {
                int k = lrow + rr * 4;
                Ws[k][lcol] = wr[(ci0 + k) * C + co0 + lcol];
                Xs[k][lcol] = valid ? g_inter[(size_t)b * CN + (size_t)(ci0 + k) * N + sidx]
                                    : 0.f;
            }
            __syncthreads();
            #pragma unroll
            for (int k = 0; k < 16; ++k) {
                float a[4], bb[4];
                #pragma unroll
                for (int e = 0; e < 4; ++e) a[e]  = Ws[k][ty * 4 + e];
                #pragma unroll
                for (int e = 0; e < 4; ++e) bb[e] = Xs[k][tx * 4 + e];
                #pragma unroll
                for (int i = 0; i < 4; ++i)
                    #pragma unroll
                    for (int j = 0; j < 4; ++j)
                        acc[i][j] = fmaf(a[i], bb[j], acc[i][j]);
            }
            __syncthreads();
        }
    }

    #pragma unroll
    for (int i = 0; i < 4; ++i) {
        int co = co0 + ty * 4 + i;
        float bias = conv_b[co];
        #pragma unroll
        for (int j = 0; j < 4; ++j) {
            int col = p0 + tx * 4 + j;
            g_y[(size_t)b * CN + (size_t)co * N + col] = acc[i][j] + bias;
        }
    }
}

// ---------------- BN stats (training: batch mean / biased var) --------------
__global__ void bn_stats_kernel(const float* __restrict__ gamma,
                                const float* __restrict__ beta) {
    int ch = blockIdx.x;
    int t  = threadIdx.x;
    float s = 0.f, sq = 0.f;
    for (int b = 0; b < BATCH; ++b) {
        const float* yp = g_y + (size_t)b * CN + (size_t)ch * N;
        for (int p = t; p < N; p += 256) {
            float v = yp[p];
            s += v; sq += v * v;
        }
    }
    __shared__ float rs[256], rq[256];
    rs[t] = s; rq[t] = sq;
    __syncthreads();
    for (int off = 128; off > 0; off >>= 1) {
        if (t < off) { rs[t] += rs[t + off]; rq[t] += rq[t + off]; }
        __syncthreads();
    }
    if (t == 0) {
        float mean = rs[0] * (1.0f / 8192.0f);
        float var  = rq[0] * (1.0f / 8192.0f) - mean * mean;
        float rstd = rsqrtf(var + 1e-5f);
        float sc = gamma[ch] * rstd;
        g_scale[ch] = sc;
        g_shift[ch] = beta[ch] - mean * sc;
    }
}

// ---------------- apply BN + ReLU -------------------------------------------
__global__ void bn_apply_kernel(float* __restrict__ out) {
    int i = blockIdx.x * 256 + threadIdx.x;   // 0 .. 2M-1
    int ch = (i >> 10) & (C - 1);
    out[i] = fmaxf(fmaf(g_y[i], g_scale[ch], g_shift[ch]), 0.f);
}

// ---------------------------------------------------------------------------
extern "C" void kernel_launch(void* const* d_in, const int* in_sizes, int n_in,
                              void* d_out, int out_size) {
    const float* x      = (const float*)d_in[0];
    const float* ind    = (const float*)d_in[1];
    const float* conv_w = (const float*)d_in[2];
    const float* conv_b = (const float*)d_in[3];
    const float* gamma  = (const float*)d_in[4];
    const float* beta   = (const float*)d_in[5];
    float* out = (float*)d_out;

    deg_part_kernel<<<dim3(4, 16, BATCH), 256>>>(ind);
    wtr_kernel<<<(9 * C * C + 255) / 256, 256>>>(conv_w);      // independent
    deg_final_kernel<<<32, 256>>>();
    xt_kernel<<<dim3(32, 8, BATCH), dim3(32, 8)>>>(x);
    gcn_gemm_kernel<<<dim3(16, 4, BATCH), 256>>>(ind, x);
    gcn_conv_kernel<<<dim3(16, 4, BATCH), 256>>>(conv_b);
    bn_stats_kernel<<<C, 256>>>(gamma, beta);
    bn_apply_kernel<<<(BATCH * CN) / 256, 256>>>(out);
}

// round 4
// speedup vs baseline: 2.4888x; 2.4888x over previous
#include <cuda_runtime.h>
#include <cuda_bf16.h>
#include <math.h>
#include <stdint.h>

// ---------------------------------------------------------------------------
// GCN: out = relu(BN(conv3x3( D^-1/2 (A+I) D^-1/2 x ))), A = ind^T per batch
// b=8, c=256, n=1024 (32x32).
// Tensor path: mma.sync m16n8k16 bf16 (sm_100 baseline PTX; tcgen05 is
// unavailable because the harness pins PTX target to compute_100 without 'a').
// Precision: 3-term bf16 hi/lo split  AhBh + AhBl + AlBh  (~2^-17).
// ---------------------------------------------------------------------------

#define BATCH 8
#define C     256
#define NPOS  1024
#define PADN  1156       // 34*34 zero-padded spatial
#define K2    2304       // 9*256 conv reduction

// ------------------------- device scratch ----------------------------------
__device__ __align__(16) float g_part[BATCH*16*NPOS];
__device__ __align__(16) float g_d[BATCH*NPOS];
__device__ __align__(16) __nv_bfloat16 g_iT_hi[BATCH*NPOS*NPOS];   // (A+I)[i][j]
__device__ __align__(16) __nv_bfloat16 g_iT_lo[BATCH*NPOS*NPOS];
__device__ __align__(16) __nv_bfloat16 g_xs_hi[BATCH*C*NPOS];      // x*d[j], [c][j]
__device__ __align__(16) __nv_bfloat16 g_xs_lo[BATCH*C*NPOS];
__device__ __align__(16) __nv_bfloat16 g_ip_hi[BATCH*PADN*C];      // inter_pad [ppos][ci]
__device__ __align__(16) __nv_bfloat16 g_ip_lo[BATCH*PADN*C];
__device__ __align__(16) __nv_bfloat16 g_w2_hi[C*K2];              // [co][tap*256+ci]
__device__ __align__(16) __nv_bfloat16 g_w2_lo[C*K2];
__device__ __align__(16) float g_y[BATCH*NPOS*C];                  // conv out [b][pos][co]
__device__ __align__(16) float g_ps[64*C], g_pq[64*C];
__device__ float g_scale[C], g_shift[C];

// ------------------------- ptx helpers -------------------------------------
__device__ __forceinline__ uint32_t smem_u32(const void* p) {
    uint32_t a;
    asm("{ .reg .u64 t; cvta.to.shared.u64 t, %1; cvt.u32.u64 %0, t; }" : "=r"(a) : "l"(p));
    return a;
}
__device__ __forceinline__ void cp16(uint32_t dst, const void* src) {
    asm volatile("cp.async.cg.shared.global [%0], [%1], 16;" :: "r"(dst), "l"(src));
}
#define CP_COMMIT() asm volatile("cp.async.commit_group;" ::: "memory")
#define CP_WAIT(n)  asm volatile("cp.async.wait_group %0;" :: "n"(n) : "memory")

__device__ __forceinline__ void ldsm4(uint32_t* d, uint32_t addr) {
    asm volatile("ldmatrix.sync.aligned.m8n8.x4.shared.b16 {%0,%1,%2,%3}, [%4];"
        : "=r"(d[0]), "=r"(d[1]), "=r"(d[2]), "=r"(d[3]) : "r"(addr));
}
__device__ __forceinline__ void mma16816(float* c, const uint32_t* a, const uint32_t* b) {
    asm volatile("mma.sync.aligned.m16n8k16.row.col.f32.bf16.bf16.f32 "
        "{%0,%1,%2,%3}, {%4,%5,%6,%7}, {%8,%9}, {%0,%1,%2,%3};"
        : "+f"(c[0]), "+f"(c[1]), "+f"(c[2]), "+f"(c[3])
        : "r"(a[0]), "r"(a[1]), "r"(a[2]), "r"(a[3]), "r"(b[0]), "r"(b[1]));
}

// ------------------------- prep kernels ------------------------------------
__global__ void deg_part_kernel(const float* __restrict__ ind) {
    int b = blockIdx.z, jc = blockIdx.y;
    int i = blockIdx.x * 256 + threadIdx.x;
    const float* p = ind + (size_t)b * NPOS * NPOS + (size_t)(jc * 64) * NPOS + i;
    float s = 0.f;
    #pragma unroll 8
    for (int jj = 0; jj < 64; ++jj) s += p[jj * NPOS];
    g_part[(b * 16 + jc) * NPOS + i] = s;
}

__global__ void deg_final_kernel() {
    int gi = blockIdx.x * 256 + threadIdx.x;
    int b = gi >> 10, i = gi & (NPOS - 1);
    float s = 0.f;
    #pragma unroll
    for (int jc = 0; jc < 16; ++jc) s += g_part[(b * 16 + jc) * NPOS + i];
    g_d[b * NPOS + i] = sqrtf(1.0f / (s + 1e-8f));
}

// transpose ind -> (A+I), split bf16 hi/lo:  g_iT[b][i][j] = ind[b][j][i] + (i==j)
__global__ void tsplit_ind_kernel(const float* __restrict__ ind) {
    __shared__ float t[32][33];
    int b = blockIdx.z;
    int i0 = blockIdx.x * 32, j0 = blockIdx.y * 32;
    int tx = threadIdx.x, ty = threadIdx.y;
    #pragma unroll
    for (int r = 0; r < 4; ++r)
        t[ty + 8 * r][tx] = ind[((size_t)(b * NPOS + j0 + ty + 8 * r)) * NPOS + i0 + tx];
    __syncthreads();
    #pragma unroll
    for (int r = 0; r < 4; ++r) {
        int il = ty + 8 * r;
        int i = i0 + il, j = j0 + tx;
        float v = t[tx][il];
        if (i == j) v += 1.0f;
        size_t e = ((size_t)(b * NPOS + i)) * NPOS + j;
        __nv_bfloat16 h = __float2bfloat16(v);
        g_iT_hi[e] = h;
        g_iT_lo[e] = __float2bfloat16(v - __bfloat162float(h));
    }
}

// xs[b][c][j] = x[b][c][j] * d[b][j], split
__global__ void xs_split_kernel(const float* __restrict__ x) {
    size_t idx = (size_t)blockIdx.x * 256 + threadIdx.x;
    int j = (int)(idx & (NPOS - 1));
    int b = (int)(idx >> 18);
    float v = x[idx] * g_d[b * NPOS + j];
    __nv_bfloat16 h = __float2bfloat16(v);
    g_xs_hi[idx] = h;
    g_xs_lo[idx] = __float2bfloat16(v - __bfloat162float(h));
}

// w2[co][tap*256+ci] = w[co][ci][tap], split
__global__ void wsplit_kernel(const float* __restrict__ w) {
    int o = blockIdx.x * 256 + threadIdx.x;   // < 256*2304
    int co = o / K2;
    int r = o - co * K2;
    int tap = r >> 8, ci = r & 255;
    float v = w[(size_t)(co * C + ci) * 9 + tap];
    __nv_bfloat16 h = __float2bfloat16(v);
    g_w2_hi[o] = h;
    g_w2_lo[o] = __float2bfloat16(v - __bfloat162float(h));
}

__global__ void pad_zero_kernel() {
    int idx = blockIdx.x * 256 + threadIdx.x;   // 1156*256 uint4 covers both arrays
    uint4 z = make_uint4(0, 0, 0, 0);
    ((uint4*)g_ip_hi)[idx] = z;
    ((uint4*)g_ip_lo)[idx] = z;
}

// ------------------------- mma.sync GEMM ------------------------------------
// MODE 1: D[pos 128][c 128]  = indT (A) . xs (B),            K=1024 (16 chunks of 64)
// MODE 2: D[pos 128][co 128] = inter_pad shifted (A) . w2,   K=2304 (36 chunks of 64)
// Stage = Ah|Al|Bh|Bl, each 128x64 bf16 (16KB), double-buffered -> 128KB smem.
static constexpr int SMEM_DYN = 2 * 65536;

template<int MODE>
__global__ void __launch_bounds__(256, 1) gemm_mma(const float* __restrict__ conv_b) {
    extern __shared__ char smem[];
    uint32_t sb = smem_u32(smem);
    const int tid = threadIdx.x;
    const int pos0 = blockIdx.x * 128, n0 = blockIdx.y * 128, b = blockIdx.z;
    constexpr int CHUNKS = (MODE == 1) ? 16 : 36;

    auto stage = [&](int c, int p) {
        uint32_t base = sb + p * 65536;
        #pragma unroll
        for (int it = 0; it < 4; ++it) {
            int u = it * 256 + tid;           // 1024 16B-units per tile
            int r = u >> 3, g = u & 7;
            uint32_t sw = (uint32_t)(r * 128 + ((g ^ (r & 7)) * 16));
            const __nv_bfloat16 *ah, *al2;
            if (MODE == 1) {
                size_t e = ((size_t)(b * NPOS + pos0 + r)) * NPOS + c * 64 + g * 8;
                ah = g_iT_hi + e; al2 = g_iT_lo + e;
            } else {
                int tap = c >> 2, ci0 = (c & 3) * 64;
                int pos = pos0 + r;
                int pp = ((pos >> 5) + 1) * 34 + (pos & 31) + 1
                         + (tap / 3 - 1) * 34 + (tap % 3 - 1);
                size_t e = ((size_t)(b * PADN + pp)) * C + ci0 + g * 8;
                ah = g_ip_hi + e; al2 = g_ip_lo + e;
            }
            cp16(base + sw, ah);
            cp16(base + 16384 + sw, al2);
            const __nv_bfloat16 *bh2, *bl2;
            if (MODE == 1) {
                size_t e = ((size_t)(b * C + n0 + r)) * NPOS + c * 64 + g * 8;
                bh2 = g_xs_hi + e; bl2 = g_xs_lo + e;
            } else {
                size_t e = ((size_t)(n0 + r)) * K2 + c * 64 + g * 8;
                bh2 = g_w2_hi + e; bl2 = g_w2_lo + e;
            }
            cp16(base + 32768 + sw, bh2);
            cp16(base + 49152 + sw, bl2);
        }
    };

    const int l = tid & 31, w = tid >> 5;
    const int wm = w >> 2, wn = w & 3;             // 2 x 4 warp grid
    const int mbase = wm * 64, nbase = wn * 32;
    const int lr = l & 15;
    const uint32_t arow = (uint32_t)((mbase + lr) * 128);
    const uint32_t brow = (uint32_t)((nbase + lr) * 128);
    uint32_t u16[4];
    #pragma unroll
    for (int kk = 0; kk < 4; ++kk)
        u16[kk] = (uint32_t)(((kk * 2 + (l >> 4)) ^ (l & 7)) * 16);

    float acc[4][4][4];
    #pragma unroll
    for (int i = 0; i < 4; ++i)
        #pragma unroll
        for (int j = 0; j < 4; ++j)
            #pragma unroll
            for (int e = 0; e < 4; ++e) acc[i][j][e] = 0.f;

    stage(0, 0); CP_COMMIT();

    for (int c = 0; c < CHUNKS; ++c) {
        int p = c & 1;
        if (c + 1 < CHUNKS) { stage(c + 1, p ^ 1); CP_COMMIT(); CP_WAIT(1); }
        else                { CP_WAIT(0); }
        __syncthreads();
        uint32_t bb = sb + p * 65536;
        #pragma unroll
        for (int kk = 0; kk < 4; ++kk) {
            uint32_t ah[4][4], al[4][4], bh[2][4], bl[2][4];
            #pragma unroll
            for (int mi = 0; mi < 4; ++mi) {
                ldsm4(ah[mi], bb + arow + mi * 2048 + u16[kk]);
                ldsm4(al[mi], bb + 16384 + arow + mi * 2048 + u16[kk]);
            }
            #pragma unroll
            for (int nb = 0; nb < 2; ++nb) {
                ldsm4(bh[nb], bb + 32768 + brow + nb * 2048 + u16[kk]);
                ldsm4(bl[nb], bb + 49152 + brow + nb * 2048 + u16[kk]);
            }
            #pragma unroll
            for (int mi = 0; mi < 4; ++mi)
                #pragma unroll
                for (int nj = 0; nj < 4; ++nj) {
                    int nb = nj >> 1, s = nj & 1;
                    uint32_t fh[2] = { bh[nb][s], bh[nb][s + 2] };
                    uint32_t fl[2] = { bl[nb][s], bl[nb][s + 2] };
                    mma16816(acc[mi][nj], ah[mi], fh);
                    mma16816(acc[mi][nj], ah[mi], fl);
                    mma16816(acc[mi][nj], al[mi], fh);
                }
        }
        __syncthreads();   // all warps done reading buffer p before it is restaged
    }

    // ---------------- epilogue ----------------
    int qr = l >> 2, qc = (l & 3) * 2;
    if (MODE == 1) {
        #pragma unroll
        for (int mi = 0; mi < 4; ++mi)
            #pragma unroll
            for (int half = 0; half < 2; ++half) {
                int pos = pos0 + mbase + mi * 16 + qr + half * 8;
                float di = g_d[b * NPOS + pos];
                int pp = ((pos >> 5) + 1) * 34 + (pos & 31) + 1;
                size_t ro = ((size_t)(b * PADN + pp)) * C + n0 + nbase + qc;
                #pragma unroll
                for (int nj = 0; nj < 4; ++nj) {
                    float v0 = di * acc[mi][nj][half * 2];
                    float v1 = di * acc[mi][nj][half * 2 + 1];
                    __nv_bfloat16 h0 = __float2bfloat16(v0), h1 = __float2bfloat16(v1);
                    __nv_bfloat162 hh; hh.x = h0; hh.y = h1;
                    __nv_bfloat162 ll;
                    ll.x = __float2bfloat16(v0 - __bfloat162float(h0));
                    ll.y = __float2bfloat16(v1 - __bfloat162float(h1));
                    *(__nv_bfloat162*)(g_ip_hi + ro + nj * 8) = hh;
                    *(__nv_bfloat162*)(g_ip_lo + ro + nj * 8) = ll;
                }
            }
    } else {
        #pragma unroll
        for (int mi = 0; mi < 4; ++mi)
            #pragma unroll
            for (int half = 0; half < 2; ++half) {
                int pos = pos0 + mbase + mi * 16 + qr + half * 8;
                size_t yo = ((size_t)(b * NPOS + pos)) * C + n0 + nbase + qc;
                #pragma unroll
                for (int nj = 0; nj < 4; ++nj) {
                    int co = n0 + nbase + nj * 8 + qc;
                    float2 v;
                    v.x = acc[mi][nj][half * 2]     + conv_b[co];
                    v.y = acc[mi][nj][half * 2 + 1] + conv_b[co + 1];
                    *(float2*)(g_y + yo + nj * 8) = v;
                }
            }
    }
}

// ------------------------- BN + output -------------------------------------
__global__ void stats1_kernel() {
    int bk = blockIdx.x, t = threadIdx.x;     // 64 blocks x 128 rows
    float s = 0.f, q = 0.f;
    const float* yp = g_y + (size_t)bk * 128 * C;
    for (int r = 0; r < 128; ++r) {
        float v = yp[(size_t)r * C + t];
        s += v; q += v * v;
    }
    g_ps[bk * C + t] = s;
    g_pq[bk * C + t] = q;
}

__global__ void stats2_kernel(const float* __restrict__ gamma,
                              const float* __restrict__ beta) {
    int t = threadIdx.x;
    float s = 0.f, q = 0.f;
    #pragma unroll
    for (int k = 0; k < 64; ++k) { s += g_ps[k * C + t]; q += g_pq[k * C + t]; }
    float mean = s * (1.0f / 8192.0f);
    float var  = q * (1.0f / 8192.0f) - mean * mean;
    float sc = gamma[t] * rsqrtf(var + 1e-5f);
    g_scale[t] = sc;
    g_shift[t] = beta[t] - mean * sc;
}

// out[b][co][pos] = relu(y[b][pos][co]*scale+shift)  (tiled transpose)
__global__ void apply_t_kernel(float* __restrict__ out) {
    __shared__ float t[32][33];
    int b = blockIdx.z;
    int p0 = blockIdx.x * 32, c0 = blockIdx.y * 32;
    int tx = threadIdx.x, ty = threadIdx.y;
    #pragma unroll
    for (int r = 0; r < 4; ++r)
        t[ty + 8 * r][tx] = g_y[((size_t)(b * NPOS + p0 + ty + 8 * r)) * C + c0 + tx];
    __syncthreads();
    #pragma unroll
    for (int r = 0; r < 4; ++r) {
        int cl = ty + 8 * r;
        float v = fmaf(t[tx][cl], g_scale[c0 + cl], g_shift[c0 + cl]);
        out[((size_t)(b * C + c0 + cl)) * NPOS + p0 + tx] = fmaxf(v, 0.f);
    }
}

// ---------------------------------------------------------------------------
extern "C" void kernel_launch(void* const* d_in, const int* in_sizes, int n_in,
                              void* d_out, int out_size) {
    const float* x      = (const float*)d_in[0];
    const float* ind    = (const float*)d_in[1];
    const float* conv_w = (const float*)d_in[2];
    const float* conv_b = (const float*)d_in[3];
    const float* gamma  = (const float*)d_in[4];
    const float* beta   = (const float*)d_in[5];
    float* out = (float*)d_out;

    cudaFuncSetAttribute(gemm_mma<1>, cudaFuncAttributeMaxDynamicSharedMemorySize, SMEM_DYN);
    cudaFuncSetAttribute(gemm_mma<2>, cudaFuncAttributeMaxDynamicSharedMemorySize, SMEM_DYN);

    deg_part_kernel<<<dim3(4, 16, BATCH), 256>>>(ind);
    tsplit_ind_kernel<<<dim3(32, 32, BATCH), dim3(32, 8)>>>(ind);
    wsplit_kernel<<<2304, 256>>>(conv_w);
    pad_zero_kernel<<<1156, 256>>>();
    deg_final_kernel<<<32, 256>>>();
    xs_split_kernel<<<8192, 256>>>(x);
    gemm_mma<1><<<dim3(8, 2, BATCH), 256, SMEM_DYN>>>(nullptr);
    gemm_mma<2><<<dim3(8, 2, BATCH), 256, SMEM_DYN>>>(conv_b);
    stats1_kernel<<<64, 256>>>();
    stats2_kernel<<<1, 256>>>(gamma, beta);
    apply_t_kernel<<<dim3(32, 8, BATCH), dim3(32, 8)>>>(out);
}

// round 5
// speedup vs baseline: 4.8353x; 1.9428x over previous
#include <cuda_runtime.h>
#include <cuda_fp16.h>
#include <math.h>
#include <stdint.h>

// ---------------------------------------------------------------------------
// GCN: out = relu(BN(conv3x3( D^-1/2 (A+I) D^-1/2 x ))), A = ind^T per batch
// b=8, c=256, n=1024 (32x32).
// R5: 1-term fp16 mma.sync (m16n8k16 f32.f16.f16.f32), 4-stage cp.async ring,
// degree sums fused into the transpose kernel.
// ---------------------------------------------------------------------------

#define BATCH 8
#define C     256
#define NPOS  1024
#define PADN  1156       // 34*34 zero-padded spatial
#define K2    2304       // 9*256 conv reduction

// ------------------------- device scratch ----------------------------------
__device__ __align__(16) float g_part[BATCH*32*NPOS];
__device__ __align__(16) float g_d[BATCH*NPOS];
__device__ __align__(16) __half g_iT[BATCH*NPOS*NPOS];   // (A+I)[i][j] fp16
__device__ __align__(16) __half g_xs[BATCH*C*NPOS];      // x*d[j], [c][j]
__device__ __align__(16) __half g_ip[BATCH*PADN*C];      // inter_pad [ppos][ci]
__device__ __align__(16) __half g_w2[C*K2];              // [co][tap*256+ci]
__device__ __align__(16) float g_y[BATCH*NPOS*C];        // conv out [b][pos][co]
__device__ __align__(16) float g_ps[64*C], g_pq[64*C];
__device__ float g_scale[C], g_shift[C];

// ------------------------- ptx helpers -------------------------------------
__device__ __forceinline__ uint32_t smem_u32(const void* p) {
    uint32_t a;
    asm("{ .reg .u64 t; cvta.to.shared.u64 t, %1; cvt.u32.u64 %0, t; }" : "=r"(a) : "l"(p));
    return a;
}
__device__ __forceinline__ void cp16(uint32_t dst, const void* src) {
    asm volatile("cp.async.cg.shared.global [%0], [%1], 16;" :: "r"(dst), "l"(src));
}
#define CP_COMMIT() asm volatile("cp.async.commit_group;" ::: "memory")
#define CP_WAIT(n)  asm volatile("cp.async.wait_group %0;" :: "n"(n) : "memory")

__device__ __forceinline__ void ldsm4(uint32_t* d, uint32_t addr) {
    asm volatile("ldmatrix.sync.aligned.m8n8.x4.shared.b16 {%0,%1,%2,%3}, [%4];"
        : "=r"(d[0]), "=r"(d[1]), "=r"(d[2]), "=r"(d[3]) : "r"(addr));
}
__device__ __forceinline__ void mma16816h(float* c, const uint32_t* a, const uint32_t* b) {
    asm volatile("mma.sync.aligned.m16n8k16.row.col.f32.f16.f16.f32 "
        "{%0,%1,%2,%3}, {%4,%5,%6,%7}, {%8,%9}, {%0,%1,%2,%3};"
        : "+f"(c[0]), "+f"(c[1]), "+f"(c[2]), "+f"(c[3])
        : "r"(a[0]), "r"(a[1]), "r"(a[2]), "r"(a[3]), "r"(b[0]), "r"(b[1]));
}

// ------------------------- prep kernels ------------------------------------
// transpose ind -> fp16 (A+I), and accumulate degree partial column sums.
__global__ void tsplit_deg_kernel(const float* __restrict__ ind) {
    __shared__ float t[32][33];
    __shared__ float red[8][32];
    int b = blockIdx.z;
    int i0 = blockIdx.x * 32, j0 = blockIdx.y * 32;
    int tx = threadIdx.x, ty = threadIdx.y;
    #pragma unroll
    for (int r = 0; r < 4; ++r)
        t[ty + 8 * r][tx] = ind[((size_t)(b * NPOS + j0 + ty + 8 * r)) * NPOS + i0 + tx];
    __syncthreads();
    // degree partials: sum over local j for column i = i0+tx
    {
        float s = 0.f;
        #pragma unroll
        for (int k = 0; k < 4; ++k) s += t[ty + 8 * k][tx];
        red[ty][tx] = s;
    }
    // transposed fp16 write: iT[i][j] = ind[j][i] (+1 on diag)
    #pragma unroll
    for (int r = 0; r < 4; ++r) {
        int il = ty + 8 * r;
        int i = i0 + il, j = j0 + tx;
        float v = t[tx][il];
        if (i == j) v += 1.0f;
        g_iT[((size_t)(b * NPOS + i)) * NPOS + j] = __float2half(v);
    }
    __syncthreads();
    if (ty == 0) {
        float s = 0.f;
        #pragma unroll
        for (int k = 0; k < 8; ++k) s += red[k][tx];
        g_part[((size_t)b * 32 + blockIdx.y) * NPOS + i0 + tx] = s;
    }
}

__global__ void deg_final_kernel() {
    int gi = blockIdx.x * 256 + threadIdx.x;
    int b = gi >> 10, i = gi & (NPOS - 1);
    float s = 0.f;
    #pragma unroll
    for (int jc = 0; jc < 32; ++jc) s += g_part[((size_t)b * 32 + jc) * NPOS + i];
    g_d[b * NPOS + i] = sqrtf(1.0f / (s + 1e-8f));
}

// xs[b][c][j] = fp16( x[b][c][j] * d[b][j] )
__global__ void xs_half_kernel(const float* __restrict__ x) {
    size_t idx = (size_t)blockIdx.x * 256 + threadIdx.x;
    int j = (int)(idx & (NPOS - 1));
    int b = (int)(idx >> 18);
    g_xs[idx] = __float2half(x[idx] * g_d[b * NPOS + j]);
}

// w2[co][tap*256+ci] = fp16( w[co][ci][tap] )
__global__ void w_half_kernel(const float* __restrict__ w) {
    int o = blockIdx.x * 256 + threadIdx.x;   // < 256*2304
    int co = o / K2;
    int r = o - co * K2;
    int tap = r >> 8, ci = r & 255;
    g_w2[o] = __float2half(w[(size_t)(co * C + ci) * 9 + tap]);
}

__global__ void pad_zero_kernel() {
    int idx = blockIdx.x * 256 + threadIdx.x;   // 1156*256*16B == sizeof(g_ip)
    ((uint4*)g_ip)[idx] = make_uint4(0, 0, 0, 0);
}

// ------------------------- fp16 mma GEMM ------------------------------------
// MODE 1: D[pos 128][c 128]  = iT (A) . xs (B),             K=1024 (16 chunks)
// MODE 2: D[pos 128][co 128] = inter_pad shifted (A) . w2,  K=2304 (36 chunks)
// Stage = A|B, each 128x64 fp16 (16KB) -> 32KB/stage, 4-stage ring = 128KB.
static constexpr int SMEM_DYN = 4 * 32768;

template<int MODE>
__global__ void __launch_bounds__(256, 1) gemm_half(const float* __restrict__ conv_b) {
    extern __shared__ char smem[];
    uint32_t sb = smem_u32(smem);
    const int tid = threadIdx.x;
    const int pos0 = blockIdx.x * 128, n0 = blockIdx.y * 128, b = blockIdx.z;
    constexpr int CHUNKS = (MODE == 1) ? 16 : 36;

    auto stage = [&](int c, int p) {
        uint32_t base = sb + p * 32768;
        #pragma unroll
        for (int it = 0; it < 4; ++it) {
            int u = it * 256 + tid;           // 1024 16B-units per tile
            int r = u >> 3, g = u & 7;
            uint32_t sw = (uint32_t)(r * 128 + ((g ^ (r & 7)) * 16));
            const __half *pa, *pb;
            if (MODE == 1) {
                pa = g_iT + ((size_t)(b * NPOS + pos0 + r)) * NPOS + c * 64 + g * 8;
                pb = g_xs + ((size_t)(b * C + n0 + r)) * NPOS + c * 64 + g * 8;
            } else {
                int tap = c >> 2, ci0 = (c & 3) * 64;
                int pos = pos0 + r;
                int pp = ((pos >> 5) + 1) * 34 + (pos & 31) + 1
                         + (tap / 3 - 1) * 34 + (tap % 3 - 1);
                pa = g_ip + ((size_t)(b * PADN + pp)) * C + ci0 + g * 8;
                pb = g_w2 + ((size_t)(n0 + r)) * K2 + c * 64 + g * 8;
            }
            cp16(base + sw, pa);
            cp16(base + 16384 + sw, pb);
        }
    };

    const int l = tid & 31, w = tid >> 5;
    const int wm = w >> 2, wn = w & 3;             // 2 x 4 warp grid
    const int mbase = wm * 64, nbase = wn * 32;
    const int lr = l & 15;
    const uint32_t arow = (uint32_t)((mbase + lr) * 128);
    const uint32_t brow = (uint32_t)((nbase + lr) * 128);
    uint32_t u16[4];
    #pragma unroll
    for (int kk = 0; kk < 4; ++kk)
        u16[kk] = (uint32_t)(((kk * 2 + (l >> 4)) ^ (l & 7)) * 16);

    float acc[4][4][4];
    #pragma unroll
    for (int i = 0; i < 4; ++i)
        #pragma unroll
        for (int j = 0; j < 4; ++j)
            #pragma unroll
            for (int e = 0; e < 4; ++e) acc[i][j][e] = 0.f;

    stage(0, 0); CP_COMMIT();
    stage(1, 1); CP_COMMIT();
    stage(2, 2); CP_COMMIT();

    for (int c = 0; c < CHUNKS; ++c) {
        CP_WAIT(2);          // chunk c landed
        __syncthreads();     // also: all warps finished compute(c-1) -> its buffer free
        if (c + 3 < CHUNKS) { stage(c + 3, (c + 3) & 3); CP_COMMIT(); }
        uint32_t bb = sb + (c & 3) * 32768;
        #pragma unroll
        for (int kk = 0; kk < 4; ++kk) {
            uint32_t ah[4][4], bh[2][4];
            #pragma unroll
            for (int mi = 0; mi < 4; ++mi)
                ldsm4(ah[mi], bb + arow + mi * 2048 + u16[kk]);
            #pragma unroll
            for (int nb = 0; nb < 2; ++nb)
                ldsm4(bh[nb], bb + 16384 + brow + nb * 2048 + u16[kk]);
            #pragma unroll
            for (int mi = 0; mi < 4; ++mi)
                #pragma unroll
                for (int nj = 0; nj < 4; ++nj) {
                    int nb = nj >> 1, s = nj & 1;
                    uint32_t fh[2] = { bh[nb][s], bh[nb][s + 2] };
                    mma16816h(acc[mi][nj], ah[mi], fh);
                }
        }
    }

    // ---------------- epilogue ----------------
    int qr = l >> 2, qc = (l & 3) * 2;
    if (MODE == 1) {
        #pragma unroll
        for (int mi = 0; mi < 4; ++mi)
            #pragma unroll
            for (int half = 0; half < 2; ++half) {
                int pos = pos0 + mbase + mi * 16 + qr + half * 8;
                float di = g_d[b * NPOS + pos];
                int pp = ((pos >> 5) + 1) * 34 + (pos & 31) + 1;
                size_t ro = ((size_t)(b * PADN + pp)) * C + n0 + nbase + qc;
                #pragma unroll
                for (int nj = 0; nj < 4; ++nj) {
                    __half2 hv;
                    hv.x = __float2half(di * acc[mi][nj][half * 2]);
                    hv.y = __float2half(di * acc[mi][nj][half * 2 + 1]);
                    *(__half2*)(g_ip + ro + nj * 8) = hv;
                }
            }
    } else {
        #pragma unroll
        for (int mi = 0; mi < 4; ++mi)
            #pragma unroll
            for (int half = 0; half < 2; ++half) {
                int pos = pos0 + mbase + mi * 16 + qr + half * 8;
                size_t yo = ((size_t)(b * NPOS + pos)) * C + n0 + nbase + qc;
                #pragma unroll
                for (int nj = 0; nj < 4; ++nj) {
                    int co = n0 + nbase + nj * 8 + qc;
                    float2 v;
                    v.x = acc[mi][nj][half * 2]     + conv_b[co];
                    v.y = acc[mi][nj][half * 2 + 1] + conv_b[co + 1];
                    *(float2*)(g_y + yo + nj * 8) = v;
                }
            }
    }
}

// ------------------------- BN + output -------------------------------------
__global__ void stats1_kernel() {
    int bk = blockIdx.x, t = threadIdx.x;     // 64 blocks x 128 rows
    float s = 0.f, q = 0.f;
    const float* yp = g_y + (size_t)bk * 128 * C;
    for (int r = 0; r < 128; ++r) {
        float v = yp[(size_t)r * C + t];
        s += v; q += v * v;
    }
    g_ps[bk * C + t] = s;
    g_pq[bk * C + t] = q;
}

__global__ void stats2_kernel(const float* __restrict__ gamma,
                              const float* __restrict__ beta) {
    int t = threadIdx.x;
    float s = 0.f, q = 0.f;
    #pragma unroll
    for (int k = 0; k < 64; ++k) { s += g_ps[k * C + t]; q += g_pq[k * C + t]; }
    float mean = s * (1.0f / 8192.0f);
    float var  = q * (1.0f / 8192.0f) - mean * mean;
    float sc = gamma[t] * rsqrtf(var + 1e-5f);
    g_scale[t] = sc;
    g_shift[t] = beta[t] - mean * sc;
}

// out[b][co][pos] = relu(y[b][pos][co]*scale+shift)  (tiled transpose)
__global__ void apply_t_kernel(float* __restrict__ out) {
    __shared__ float t[32][33];
    int b = blockIdx.z;
    int p0 = blockIdx.x * 32, c0 = blockIdx.y * 32;
    int tx = threadIdx.x, ty = threadIdx.y;
    #pragma unroll
    for (int r = 0; r < 4; ++r)
        t[ty + 8 * r][tx] = g_y[((size_t)(b * NPOS + p0 + ty + 8 * r)) * C + c0 + tx];
    __syncthreads();
    #pragma unroll
    for (int r = 0; r < 4; ++r) {
        int cl = ty + 8 * r;
        float v = fmaf(t[tx][cl], g_scale[c0 + cl], g_shift[c0 + cl]);
        out[((size_t)(b * C + c0 + cl)) * NPOS + p0 + tx] = fmaxf(v, 0.f);
    }
}

// ---------------------------------------------------------------------------
extern "C" void kernel_launch(void* const* d_in, const int* in_sizes, int n_in,
                              void* d_out, int out_size) {
    const float* x      = (const float*)d_in[0];
    const float* ind    = (const float*)d_in[1];
    const float* conv_w = (const float*)d_in[2];
    const float* conv_b = (const float*)d_in[3];
    const float* gamma  = (const float*)d_in[4];
    const float* beta   = (const float*)d_in[5];
    float* out = (float*)d_out;

    cudaFuncSetAttribute(gemm_half<1>, cudaFuncAttributeMaxDynamicSharedMemorySize, SMEM_DYN);
    cudaFuncSetAttribute(gemm_half<2>, cudaFuncAttributeMaxDynamicSharedMemorySize, SMEM_DYN);

    tsplit_deg_kernel<<<dim3(32, 32, BATCH), dim3(32, 8)>>>(ind);
    w_half_kernel<<<2304, 256>>>(conv_w);
    pad_zero_kernel<<<1156, 256>>>();
    deg_final_kernel<<<32, 256>>>();
    xs_half_kernel<<<8192, 256>>>(x);
    gemm_half<1><<<dim3(8, 2, BATCH), 256, SMEM_DYN>>>(nullptr);
    gemm_half<2><<<dim3(8, 2, BATCH), 256, SMEM_DYN>>>(conv_b);
    stats1_kernel<<<64, 256>>>();
    stats2_kernel<<<1, 256>>>(gamma, beta);
    apply_t_kernel<<<dim3(32, 8, BATCH), dim3(32, 8)>>>(out);
}

// round 7
// speedup vs baseline: 5.1439x; 1.0638x over previous
#include <cuda_runtime.h>
#include <cuda_fp16.h>
#include <math.h>
#include <stdint.h>

// ---------------------------------------------------------------------------
// GCN: out = relu(BN(conv3x3( D^-1/2 (A+I) D^-1/2 x ))), A = ind^T per batch
// b=8, c=256, n=1024 (32x32).
// R7 = resubmission of R6 (infra container failure; audit found no defect):
// fp16 mma.sync GEMMs + rebuilt memory-side:
//  - 64x64 float4 transpose+split with fused, coalesced degree partials
//  - gemm2 epilogue: smem transpose -> g_y in [b][co][pos] + fused BN partials
//  - gemm1 epilogue: smem staging -> coalesced g_ip row writes
// ---------------------------------------------------------------------------

#define BATCH 8
#define C     256
#define NPOS  1024
#define PADN  1156       // 34*34 zero-padded spatial
#define K2    2304       // 9*256 conv reduction

// ------------------------- device scratch ----------------------------------
__device__ __align__(16) float g_part[BATCH*NPOS*16];    // [b][i][jt] coalesced
__device__ __align__(16) float g_d[BATCH*NPOS];
__device__ __align__(16) __half g_iT[BATCH*NPOS*NPOS];   // (A+I)[i][j] fp16
__device__ __align__(16) __half g_xs[BATCH*C*NPOS];      // x*d[j], [c][j]
__device__ __align__(16) __half g_ip[BATCH*PADN*C];      // inter_pad [ppos][ci]
__device__ __align__(16) __half g_w2[C*K2];              // [co][tap*256+ci]
__device__ __align__(16) float g_y[BATCH*C*NPOS];        // conv out [b][co][pos]
__device__ __align__(16) float g_ps[64*C], g_pq[64*C];
__device__ float g_scale[C], g_shift[C];

// ------------------------- ptx helpers -------------------------------------
__device__ __forceinline__ uint32_t smem_u32(const void* p) {
    uint32_t a;
    asm("{ .reg .u64 t; cvta.to.shared.u64 t, %1; cvt.u32.u64 %0, t; }" : "=r"(a) : "l"(p));
    return a;
}
__device__ __forceinline__ void cp16(uint32_t dst, const void* src) {
    asm volatile("cp.async.cg.shared.global [%0], [%1], 16;" :: "r"(dst), "l"(src));
}
#define CP_COMMIT() asm volatile("cp.async.commit_group;" ::: "memory")
#define CP_WAIT(n)  asm volatile("cp.async.wait_group %0;" :: "n"(n) : "memory")

__device__ __forceinline__ void ldsm4(uint32_t* d, uint32_t addr) {
    asm volatile("ldmatrix.sync.aligned.m8n8.x4.shared.b16 {%0,%1,%2,%3}, [%4];"
        : "=r"(d[0]), "=r"(d[1]), "=r"(d[2]), "=r"(d[3]) : "r"(addr));
}
__device__ __forceinline__ void mma16816h(float* c, const uint32_t* a, const uint32_t* b) {
    asm volatile("mma.sync.aligned.m16n8k16.row.col.f32.f16.f16.f32 "
        "{%0,%1,%2,%3}, {%4,%5,%6,%7}, {%8,%9}, {%0,%1,%2,%3};"
        : "+f"(c[0]), "+f"(c[1]), "+f"(c[2]), "+f"(c[3])
        : "r"(a[0]), "r"(a[1]), "r"(a[2]), "r"(a[3]), "r"(b[0]), "r"(b[1]));
}

// ------------------------- prep kernels ------------------------------------
// 64x64 tile transpose ind -> fp16 (A+I); fused degree partials (pre-identity).
__global__ void __launch_bounds__(256) tsplit_deg_kernel(const float* __restrict__ ind) {
    __shared__ float t[64][65];
    int b = blockIdx.z;
    int i0 = blockIdx.x * 64, j0 = blockIdx.y * 64;
    int tid = threadIdx.x;

    // load 64 rows (j) x 64 cols (i), float4
    {
        int r = tid >> 2, q = tid & 3;
        const float* src = ind + ((size_t)(b * NPOS + j0 + r)) * NPOS + i0;
        #pragma unroll
        for (int k = 0; k < 4; ++k) {
            float4 v = *(const float4*)(src + q * 4 + k * 16);
            t[r][q * 4 + k * 16]     = v.x;
            t[r][q * 4 + k * 16 + 1] = v.y;
            t[r][q * 4 + k * 16 + 2] = v.z;
            t[r][q * 4 + k * 16 + 3] = v.w;
        }
    }
    __syncthreads();

    // write transposed fp16 + warp-reduced degree partials
    int jh = tid & 31;                 // lane: half2 j index
    int wi = tid >> 5;                 // warp -> i row group
    #pragma unroll
    for (int iter = 0; iter < 8; ++iter) {
        int il = wi + iter * 8;
        int i = i0 + il;
        float r0 = t[2 * jh][il];
        float r1 = t[2 * jh + 1][il];
        float s = r0 + r1;             // degree BEFORE identity
        float v0 = r0 + ((i == j0 + 2 * jh)     ? 1.f : 0.f);
        float v1 = r1 + ((i == j0 + 2 * jh + 1) ? 1.f : 0.f);
        *(__half2*)(g_iT + ((size_t)(b * NPOS + i)) * NPOS + j0 + 2 * jh) =
            __floats2half2_rn(v0, v1);
        #pragma unroll
        for (int off = 16; off > 0; off >>= 1)
            s += __shfl_xor_sync(0xffffffffu, s, off);
        if (jh == 0)
            g_part[((size_t)(b * NPOS + i)) * 16 + blockIdx.y] = s;
    }
}

__global__ void deg_final_kernel() {
    int gi = blockIdx.x * 256 + threadIdx.x;   // (b,i) 0..8191
    const float4* p = (const float4*)(g_part + (size_t)gi * 16);
    float s = 0.f;
    #pragma unroll
    for (int k = 0; k < 4; ++k) {
        float4 v = p[k];
        s += (v.x + v.y) + (v.z + v.w);
    }
    g_d[gi] = sqrtf(1.0f / (s + 1e-8f));
}

// xs[b][c][j] = fp16( x[b][c][j] * d[b][j] )
__global__ void xs_half_kernel(const float* __restrict__ x) {
    size_t idx = (size_t)blockIdx.x * 256 + threadIdx.x;
    int j = (int)(idx & (NPOS - 1));
    int b = (int)(idx >> 18);
    g_xs[idx] = __float2half(x[idx] * g_d[b * NPOS + j]);
}

// w2[co][tap*256+ci] = fp16( w[co][ci][tap] )
__global__ void w_half_kernel(const float* __restrict__ w) {
    int o = blockIdx.x * 256 + threadIdx.x;   // < 256*2304
    int co = o / K2;
    int r = o - co * K2;
    int tap = r >> 8, ci = r & 255;
    g_w2[o] = __float2half(w[(size_t)(co * C + ci) * 9 + tap]);
}

__global__ void pad_zero_kernel() {
    int idx = blockIdx.x * 256 + threadIdx.x;   // 1156*256 uint4 == sizeof(g_ip)
    ((uint4*)g_ip)[idx] = make_uint4(0, 0, 0, 0);
}

// ------------------------- fp16 mma GEMM ------------------------------------
// MODE 1: D[pos 128][c 128]  = iT (A) . xs (B),             K=1024 (16 chunks)
// MODE 2: D[pos 128][co 128] = inter_pad shifted (A) . w2,  K=2304 (36 chunks)
// Stage = A|B, each 128x64 fp16 (16KB) -> 32KB/stage, 4-stage ring = 128KB.
// Epilogues reuse the ring smem for transposed/coalesced output staging.
static constexpr int SMEM_DYN = 4 * 32768;

template<int MODE>
__global__ void __launch_bounds__(256, 1) gemm_half(const float* __restrict__ conv_b) {
    extern __shared__ char smem[];
    uint32_t sb = smem_u32(smem);
    const int tid = threadIdx.x;
    const int pos0 = blockIdx.x * 128, n0 = blockIdx.y * 128, b = blockIdx.z;
    constexpr int CHUNKS = (MODE == 1) ? 16 : 36;

    auto stage = [&](int c, int p) {
        uint32_t base = sb + p * 32768;
        #pragma unroll
        for (int it = 0; it < 4; ++it) {
            int u = it * 256 + tid;           // 1024 16B-units per tile
            int r = u >> 3, g = u & 7;
            uint32_t sw = (uint32_t)(r * 128 + ((g ^ (r & 7)) * 16));
            const __half *pa, *pb;
            if (MODE == 1) {
                pa = g_iT + ((size_t)(b * NPOS + pos0 + r)) * NPOS + c * 64 + g * 8;
                pb = g_xs + ((size_t)(b * C + n0 + r)) * NPOS + c * 64 + g * 8;
            } else {
                int tap = c >> 2, ci0 = (c & 3) * 64;
                int pos = pos0 + r;
                int pp = ((pos >> 5) + 1) * 34 + (pos & 31) + 1
                         + (tap / 3 - 1) * 34 + (tap % 3 - 1);
                pa = g_ip + ((size_t)(b * PADN + pp)) * C + ci0 + g * 8;
                pb = g_w2 + ((size_t)(n0 + r)) * K2 + c * 64 + g * 8;
            }
            cp16(base + sw, pa);
            cp16(base + 16384 + sw, pb);
        }
    };

    const int l = tid & 31, w = tid >> 5;
    const int wm = w >> 2, wn = w & 3;             // 2 x 4 warp grid
    const int mbase = wm * 64, nbase = wn * 32;
    const int lr = l & 15;
    const uint32_t arow = (uint32_t)((mbase + lr) * 128);
    const uint32_t brow = (uint32_t)((nbase + lr) * 128);
    uint32_t u16[4];
    #pragma unroll
    for (int kk = 0; kk < 4; ++kk)
        u16[kk] = (uint32_t)(((kk * 2 + (l >> 4)) ^ (l & 7)) * 16);

    float acc[4][4][4];
    #pragma unroll
    for (int i = 0; i < 4; ++i)
        #pragma unroll
        for (int j = 0; j < 4; ++j)
            #pragma unroll
            for (int e = 0; e < 4; ++e) acc[i][j][e] = 0.f;

    stage(0, 0); CP_COMMIT();
    stage(1, 1); CP_COMMIT();
    stage(2, 2); CP_COMMIT();

    for (int c = 0; c < CHUNKS; ++c) {
        CP_WAIT(2);          // chunk c landed
        __syncthreads();     // all warps finished compute(c-1) -> its buffer free
        if (c + 3 < CHUNKS) { stage(c + 3, (c + 3) & 3); CP_COMMIT(); }
        uint32_t bb = sb + (c & 3) * 32768;
        #pragma unroll
        for (int kk = 0; kk < 4; ++kk) {
            uint32_t ah[4][4], bh[2][4];
            #pragma unroll
            for (int mi = 0; mi < 4; ++mi)
                ldsm4(ah[mi], bb + arow + mi * 2048 + u16[kk]);
            #pragma unroll
            for (int nb = 0; nb < 2; ++nb)
                ldsm4(bh[nb], bb + 16384 + brow + nb * 2048 + u16[kk]);
            #pragma unroll
            for (int mi = 0; mi < 4; ++mi)
                #pragma unroll
                for (int nj = 0; nj < 4; ++nj) {
                    int nb = nj >> 1, s = nj & 1;
                    uint32_t fh[2] = { bh[nb][s], bh[nb][s + 2] };
                    mma16816h(acc[mi][nj], ah[mi], fh);
                }
        }
    }
    __syncthreads();          // ring smem free for epilogue reuse

    // ---------------- epilogue ----------------
    int qr = l >> 2, qc = (l & 3) * 2;
    if (MODE == 1) {
        // stage fp16 tile [pos][ci] in smem, then coalesced 256B row writes
        __half* ips = (__half*)smem;               // [128][136]
        #pragma unroll
        for (int mi = 0; mi < 4; ++mi)
            #pragma unroll
            for (int half = 0; half < 2; ++half) {
                int pl = mbase + mi * 16 + qr + half * 8;
                float di = g_d[b * NPOS + pos0 + pl];
                #pragma unroll
                for (int nj = 0; nj < 4; ++nj) {
                    *(__half2*)(ips + pl * 136 + nbase + nj * 8 + qc) =
                        __floats2half2_rn(di * acc[mi][nj][half * 2],
                                          di * acc[mi][nj][half * 2 + 1]);
                }
            }
        __syncthreads();
        int row = tid >> 1, part = tid & 1;
        int pos = pos0 + row;
        int pp = ((pos >> 5) + 1) * 34 + (pos & 31) + 1;
        uint4* dst = (uint4*)(g_ip + ((size_t)(b * PADN + pp)) * C + n0) + part * 8;
        const uint4* srcp = (const uint4*)(ips + row * 136) + part * 8;
        #pragma unroll
        for (int k = 0; k < 8; ++k) dst[k] = srcp[k];
    } else {
        // stage fp32 tile transposed [co][pos] in smem; stream rows + BN partials
        float* ys = (float*)smem;                  // [128][132]
        #pragma unroll
        for (int mi = 0; mi < 4; ++mi)
            #pragma unroll
            for (int half = 0; half < 2; ++half) {
                int pl = mbase + mi * 16 + qr + half * 8;
                #pragma unroll
                for (int nj = 0; nj < 4; ++nj) {
                    int cl = nbase + nj * 8 + qc;
                    ys[cl * 132 + pl]       = acc[mi][nj][half * 2]     + conv_b[n0 + cl];
                    ys[(cl + 1) * 132 + pl] = acc[mi][nj][half * 2 + 1] + conv_b[n0 + cl + 1];
                }
            }
        __syncthreads();
        int cl = tid >> 1, part = tid & 1;
        const float4* rowp = (const float4*)(ys + cl * 132 + part * 64);
        float4* dst = (float4*)(g_y + ((size_t)(b * C + n0 + cl)) * NPOS + pos0 + part * 64);
        float s = 0.f, q = 0.f;
        #pragma unroll
        for (int k = 0; k < 16; ++k) {
            float4 v = rowp[k];
            s += (v.x + v.y) + (v.z + v.w);
            q += (v.x * v.x + v.y * v.y) + (v.z * v.z + v.w * v.w);
            dst[k] = v;
        }
        s += __shfl_xor_sync(0xffffffffu, s, 1);
        q += __shfl_xor_sync(0xffffffffu, q, 1);
        if (!part) {
            int slot = blockIdx.x * 8 + blockIdx.z;     // 0..63
            g_ps[slot * C + n0 + cl] = s;
            g_pq[slot * C + n0 + cl] = q;
        }
    }
}

// ------------------------- BN + output -------------------------------------
__global__ void stats2_kernel(const float* __restrict__ gamma,
                              const float* __restrict__ beta) {
    int t = threadIdx.x;
    float s = 0.f, q = 0.f;
    #pragma unroll
    for (int k = 0; k < 64; ++k) { s += g_ps[k * C + t]; q += g_pq[k * C + t]; }
    float mean = s * (1.0f / 8192.0f);
    float var  = q * (1.0f / 8192.0f) - mean * mean;
    float sc = gamma[t] * rsqrtf(var + 1e-5f);
    g_scale[t] = sc;
    g_shift[t] = beta[t] - mean * sc;
}

// out = relu(y*scale+shift), y already in [b][co][pos] layout -> elementwise
__global__ void apply_kernel(float* __restrict__ out) {
    int i4 = blockIdx.x * 256 + threadIdx.x;    // float4 index, 524288 total
    int co = (i4 >> 8) & (C - 1);
    float sc = g_scale[co], sh = g_shift[co];
    float4 v = ((const float4*)g_y)[i4];
    v.x = fmaxf(fmaf(v.x, sc, sh), 0.f);
    v.y = fmaxf(fmaf(v.y, sc, sh), 0.f);
    v.z = fmaxf(fmaf(v.z, sc, sh), 0.f);
    v.w = fmaxf(fmaf(v.w, sc, sh), 0.f);
    ((float4*)out)[i4] = v;
}

// ---------------------------------------------------------------------------
extern "C" void kernel_launch(void* const* d_in, const int* in_sizes, int n_in,
                              void* d_out, int out_size) {
    const float* x      = (const float*)d_in[0];
    const float* ind    = (const float*)d_in[1];
    const float* conv_w = (const float*)d_in[2];
    const float* conv_b = (const float*)d_in[3];
    const float* gamma  = (const float*)d_in[4];
    const float* beta   = (const float*)d_in[5];
    float* out = (float*)d_out;

    cudaFuncSetAttribute(gemm_half<1>, cudaFuncAttributeMaxDynamicSharedMemorySize, SMEM_DYN);
    cudaFuncSetAttribute(gemm_half<2>, cudaFuncAttributeMaxDynamicSharedMemorySize, SMEM_DYN);

    tsplit_deg_kernel<<<dim3(16, 16, BATCH), 256>>>(ind);
    w_half_kernel<<<2304, 256>>>(conv_w);
    pad_zero_kernel<<<1156, 256>>>();
    deg_final_kernel<<<32, 256>>>();
    xs_half_kernel<<<8192, 256>>>(x);
    gemm_half<1><<<dim3(8, 2, BATCH), 256, SMEM_DYN>>>(nullptr);
    gemm_half<2><<<dim3(8, 2, BATCH), 256, SMEM_DYN>>>(conv_b);
    stats2_kernel<<<1, 256>>>(gamma, beta);
    apply_kernel<<<2048, 256>>>(out);
}

// round 8
// speedup vs baseline: 5.3707x; 1.0441x over previous
#include <cuda_runtime.h>
#include <cuda_fp16.h>
#include <math.h>
#include <stdint.h>

// ---------------------------------------------------------------------------
// GCN: out = relu(BN(conv3x3( D^-1/2 (A+I) D^-1/2 x ))), A = ind^T per batch
// b=8, c=256, n=1024 (32x32).
// R8: launch-count reduction (9 -> 6): combo prep kernel (w_half + border pad
// + deg_final), BN stats fused into apply. GEMM cores unchanged from R7.
// ---------------------------------------------------------------------------

#define BATCH 8
#define C     256
#define NPOS  1024
#define PADN  1156       // 34*34 zero-padded spatial
#define K2    2304       // 9*256 conv reduction

// ------------------------- device scratch ----------------------------------
__device__ __align__(16) float g_part[BATCH*NPOS*16];    // [b][i][jt] coalesced
__device__ __align__(16) float g_d[BATCH*NPOS];
__device__ __align__(16) __half g_iT[BATCH*NPOS*NPOS];   // (A+I)[i][j] fp16
__device__ __align__(16) __half g_xs[BATCH*C*NPOS];      // x*d[j], [c][j]
__device__ __align__(16) __half g_ip[BATCH*PADN*C];      // inter_pad [ppos][ci]
__device__ __align__(16) __half g_w2[C*K2];              // [co][tap*256+ci]
__device__ __align__(16) float g_y[BATCH*C*NPOS];        // conv out [b][co][pos]
__device__ __align__(16) float g_ps[C*64], g_pq[C*64];   // [co][slot]

// ------------------------- ptx helpers -------------------------------------
__device__ __forceinline__ uint32_t smem_u32(const void* p) {
    uint32_t a;
    asm("{ .reg .u64 t; cvta.to.shared.u64 t, %1; cvt.u32.u64 %0, t; }" : "=r"(a) : "l"(p));
    return a;
}
__device__ __forceinline__ void cp16(uint32_t dst, const void* src) {
    asm volatile("cp.async.cg.shared.global [%0], [%1], 16;" :: "r"(dst), "l"(src));
}
#define CP_COMMIT() asm volatile("cp.async.commit_group;" ::: "memory")
#define CP_WAIT(n)  asm volatile("cp.async.wait_group %0;" :: "n"(n) : "memory")

__device__ __forceinline__ void ldsm4(uint32_t* d, uint32_t addr) {
    asm volatile("ldmatrix.sync.aligned.m8n8.x4.shared.b16 {%0,%1,%2,%3}, [%4];"
        : "=r"(d[0]), "=r"(d[1]), "=r"(d[2]), "=r"(d[3]) : "r"(addr));
}
__device__ __forceinline__ void mma16816h(float* c, const uint32_t* a, const uint32_t* b) {
    asm volatile("mma.sync.aligned.m16n8k16.row.col.f32.f16.f16.f32 "
        "{%0,%1,%2,%3}, {%4,%5,%6,%7}, {%8,%9}, {%0,%1,%2,%3};"
        : "+f"(c[0]), "+f"(c[1]), "+f"(c[2]), "+f"(c[3])
        : "r"(a[0]), "r"(a[1]), "r"(a[2]), "r"(a[3]), "r"(b[0]), "r"(b[1]));
}

// ------------------------- prep kernels ------------------------------------
// 64x64 tile transpose ind -> fp16 (A+I); fused degree partials (pre-identity).
__global__ void __launch_bounds__(256) tsplit_deg_kernel(const float* __restrict__ ind) {
    __shared__ float t[64][65];
    int b = blockIdx.z;
    int i0 = blockIdx.x * 64, j0 = blockIdx.y * 64;
    int tid = threadIdx.x;

    {   // load 64 rows (j) x 64 cols (i), float4
        int r = tid >> 2, q = tid & 3;
        const float* src = ind + ((size_t)(b * NPOS + j0 + r)) * NPOS + i0;
        #pragma unroll
        for (int k = 0; k < 4; ++k) {
            float4 v = *(const float4*)(src + q * 4 + k * 16);
            t[r][q * 4 + k * 16]     = v.x;
            t[r][q * 4 + k * 16 + 1] = v.y;
            t[r][q * 4 + k * 16 + 2] = v.z;
            t[r][q * 4 + k * 16 + 3] = v.w;
        }
    }
    __syncthreads();

    int jh = tid & 31;                 // lane: half2 j index
    int wi = tid >> 5;                 // warp -> i row group
    #pragma unroll
    for (int iter = 0; iter < 8; ++iter) {
        int il = wi + iter * 8;
        int i = i0 + il;
        float r0 = t[2 * jh][il];
        float r1 = t[2 * jh + 1][il];
        float s = r0 + r1;             // degree BEFORE identity
        float v0 = r0 + ((i == j0 + 2 * jh)     ? 1.f : 0.f);
        float v1 = r1 + ((i == j0 + 2 * jh + 1) ? 1.f : 0.f);
        *(__half2*)(g_iT + ((size_t)(b * NPOS + i)) * NPOS + j0 + 2 * jh) =
            __floats2half2_rn(v0, v1);
        #pragma unroll
        for (int off = 16; off > 0; off >>= 1)
            s += __shfl_xor_sync(0xffffffffu, s, off);
        if (jh == 0)
            g_part[((size_t)(b * NPOS + i)) * 16 + blockIdx.y] = s;
    }
}

// combo: [0,2304) w->fp16 relayout | [2304,2436) pad border | [2436,2468) deg
__global__ void combo_kernel(const float* __restrict__ w) {
    int blk = blockIdx.x, tid = threadIdx.x;
    if (blk < 2304) {
        int o = blk * 256 + tid;              // < 256*2304
        int co = o / K2;
        int r = o - co * K2;
        int tap = r >> 8, ci = r & 255;
        g_w2[o] = __float2half(w[(size_t)(co * C + ci) * 9 + tap]);
    } else if (blk < 2436) {
        int k = blk - 2304;                   // border row 0..131
        int pp;
        if (k < 34)      pp = k;                              // top row
        else if (k < 68) pp = 33 * 34 + (k - 34);             // bottom row
        else {
            int m = k - 68;
            pp = (1 + (m >> 1)) * 34 + ((m & 1) ? 33 : 0);    // side cols
        }
        int b = tid >> 5, u = tid & 31;       // 8 batches x 32 uint4 = 256B row
        ((uint4*)(g_ip + ((size_t)(b * PADN + pp)) * C))[u] = make_uint4(0, 0, 0, 0);
    } else {
        int gi = (blk - 2436) * 256 + tid;    // (b,i) 0..8191
        const float4* p = (const float4*)(g_part + (size_t)gi * 16);
        float s = 0.f;
        #pragma unroll
        for (int k = 0; k < 4; ++k) {
            float4 v = p[k];
            s += (v.x + v.y) + (v.z + v.w);
        }
        g_d[gi] = sqrtf(1.0f / (s + 1e-8f));
    }
}

// xs[b][c][j] = fp16( x[b][c][j] * d[b][j] )
__global__ void xs_half_kernel(const float* __restrict__ x) {
    size_t idx = (size_t)blockIdx.x * 256 + threadIdx.x;
    int j = (int)(idx & (NPOS - 1));
    int b = (int)(idx >> 18);
    g_xs[idx] = __float2half(x[idx] * g_d[b * NPOS + j]);
}

// ------------------------- fp16 mma GEMM ------------------------------------
// MODE 1: D[pos 128][c 128]  = iT (A) . xs (B),             K=1024 (16 chunks)
// MODE 2: D[pos 128][co 128] = inter_pad shifted (A) . w2,  K=2304 (36 chunks)
// Stage = A|B, each 128x64 fp16 (16KB) -> 32KB/stage, 4-stage ring = 128KB.
static constexpr int SMEM_DYN = 4 * 32768;

template<int MODE>
__global__ void __launch_bounds__(256, 1) gemm_half(const float* __restrict__ conv_b) {
    extern __shared__ char smem[];
    uint32_t sb = smem_u32(smem);
    const int tid = threadIdx.x;
    const int pos0 = blockIdx.x * 128, n0 = blockIdx.y * 128, b = blockIdx.z;
    constexpr int CHUNKS = (MODE == 1) ? 16 : 36;

    auto stage = [&](int c, int p) {
        uint32_t base = sb + p * 32768;
        #pragma unroll
        for (int it = 0; it < 4; ++it) {
            int u = it * 256 + tid;           // 1024 16B-units per tile
            int r = u >> 3, g = u & 7;
            uint32_t sw = (uint32_t)(r * 128 + ((g ^ (r & 7)) * 16));
            const __half *pa, *pb;
            if (MODE == 1) {
                pa = g_iT + ((size_t)(b * NPOS + pos0 + r)) * NPOS + c * 64 + g * 8;
                pb = g_xs + ((size_t)(b * C + n0 + r)) * NPOS + c * 64 + g * 8;
            } else {
                int tap = c >> 2, ci0 = (c & 3) * 64;
                int pos = pos0 + r;
                int pp = ((pos >> 5) + 1) * 34 + (pos & 31) + 1
                         + (tap / 3 - 1) * 34 + (tap % 3 - 1);
                pa = g_ip + ((size_t)(b * PADN + pp)) * C + ci0 + g * 8;
                pb = g_w2 + ((size_t)(n0 + r)) * K2 + c * 64 + g * 8;
            }
            cp16(base + sw, pa);
            cp16(base + 16384 + sw, pb);
        }
    };

    const int l = tid & 31, w = tid >> 5;
    const int wm = w >> 2, wn = w & 3;             // 2 x 4 warp grid
    const int mbase = wm * 64, nbase = wn * 32;
    const int lr = l & 15;
    const uint32_t arow = (uint32_t)((mbase + lr) * 128);
    const uint32_t brow = (uint32_t)((nbase + lr) * 128);
    uint32_t u16[4];
    #pragma unroll
    for (int kk = 0; kk < 4; ++kk)
        u16[kk] = (uint32_t)(((kk * 2 + (l >> 4)) ^ (l & 7)) * 16);

    float acc[4][4][4];
    #pragma unroll
    for (int i = 0; i < 4; ++i)
        #pragma unroll
        for (int j = 0; j < 4; ++j)
            #pragma unroll
            for (int e = 0; e < 4; ++e) acc[i][j][e] = 0.f;

    stage(0, 0); CP_COMMIT();
    stage(1, 1); CP_COMMIT();
    stage(2, 2); CP_COMMIT();

    for (int c = 0; c < CHUNKS; ++c) {
        CP_WAIT(2);          // chunk c landed
        __syncthreads();     // all warps finished compute(c-1) -> its buffer free
        if (c + 3 < CHUNKS) { stage(c + 3, (c + 3) & 3); CP_COMMIT(); }
        uint32_t bb = sb + (c & 3) * 32768;
        #pragma unroll
        for (int kk = 0; kk < 4; ++kk) {
            uint32_t ah[4][4], bh[2][4];
            #pragma unroll
            for (int mi = 0; mi < 4; ++mi)
                ldsm4(ah[mi], bb + arow + mi * 2048 + u16[kk]);
            #pragma unroll
            for (int nb = 0; nb < 2; ++nb)
                ldsm4(bh[nb], bb + 16384 + brow + nb * 2048 + u16[kk]);
            #pragma unroll
            for (int mi = 0; mi < 4; ++mi)
                #pragma unroll
                for (int nj = 0; nj < 4; ++nj) {
                    int nb = nj >> 1, s = nj & 1;
                    uint32_t fh[2] = { bh[nb][s], bh[nb][s + 2] };
                    mma16816h(acc[mi][nj], ah[mi], fh);
                }
        }
    }
    __syncthreads();          // ring smem free for epilogue reuse

    // ---------------- epilogue ----------------
    int qr = l >> 2, qc = (l & 3) * 2;
    if (MODE == 1) {
        // stage fp16 tile [pos][ci] in smem, then coalesced 256B row writes
        __half* ips = (__half*)smem;               // [128][136]
        #pragma unroll
        for (int mi = 0; mi < 4; ++mi)
            #pragma unroll
            for (int half = 0; half < 2; ++half) {
                int pl = mbase + mi * 16 + qr + half * 8;
                float di = g_d[b * NPOS + pos0 + pl];
                #pragma unroll
                for (int nj = 0; nj < 4; ++nj) {
                    *(__half2*)(ips + pl * 136 + nbase + nj * 8 + qc) =
                        __floats2half2_rn(di * acc[mi][nj][half * 2],
                                          di * acc[mi][nj][half * 2 + 1]);
                }
            }
        __syncthreads();
        int row = tid >> 1, part = tid & 1;
        int pos = pos0 + row;
        int pp = ((pos >> 5) + 1) * 34 + (pos & 31) + 1;
        uint4* dst = (uint4*)(g_ip + ((size_t)(b * PADN + pp)) * C + n0) + part * 8;
        const uint4* srcp = (const uint4*)(ips + row * 136) + part * 8;
        #pragma unroll
        for (int k = 0; k < 8; ++k) dst[k] = srcp[k];
    } else {
        // stage fp32 tile transposed [co][pos] in smem; stream rows + BN partials
        float* ys = (float*)smem;                  // [128][132]
        #pragma unroll
        for (int mi = 0; mi < 4; ++mi)
            #pragma unroll
            for (int half = 0; half < 2; ++half) {
                int pl = mbase + mi * 16 + qr + half * 8;
                #pragma unroll
                for (int nj = 0; nj < 4; ++nj) {
                    int cl = nbase + nj * 8 + qc;
                    ys[cl * 132 + pl]       = acc[mi][nj][half * 2]     + conv_b[n0 + cl];
                    ys[(cl + 1) * 132 + pl] = acc[mi][nj][half * 2 + 1] + conv_b[n0 + cl + 1];
                }
            }
        __syncthreads();
        int cl = tid >> 1, part = tid & 1;
        const float4* rowp = (const float4*)(ys + cl * 132 + part * 64);
        float4* dst = (float4*)(g_y + ((size_t)(b * C + n0 + cl)) * NPOS + pos0 + part * 64);
        float s = 0.f, q = 0.f;
        #pragma unroll
        for (int k = 0; k < 16; ++k) {
            float4 v = rowp[k];
            s += (v.x + v.y) + (v.z + v.w);
            q += (v.x * v.x + v.y * v.y) + (v.z * v.z + v.w * v.w);
            dst[k] = v;
        }
        s += __shfl_xor_sync(0xffffffffu, s, 1);
        q += __shfl_xor_sync(0xffffffffu, q, 1);
        if (!part) {
            int slot = blockIdx.x * 8 + blockIdx.z;     // 0..63
            g_ps[(n0 + cl) * 64 + slot] = s;
            g_pq[(n0 + cl) * 64 + slot] = q;
        }
    }
}

// ------------------------- fused BN stats + apply ---------------------------
// one block = one (b,co) row of g_y (1024 floats = 256 float4)
__global__ void apply_kernel(float* __restrict__ out,
                             const float* __restrict__ gamma,
                             const float* __restrict__ beta) {
    __shared__ float sps[64], spq[64];
    int tid = threadIdx.x;
    int co = blockIdx.x & (C - 1);
    if (tid < 64)       sps[tid] = g_ps[co * 64 + tid];
    else if (tid < 128) spq[tid - 64] = g_pq[co * 64 + tid - 64];
    __syncthreads();
    float s = 0.f, q = 0.f;
    #pragma unroll
    for (int k = 0; k < 64; ++k) { s += sps[k]; q += spq[k]; }
    float mean = s * (1.0f / 8192.0f);
    float var  = q * (1.0f / 8192.0f) - mean * mean;
    float sc = gamma[co] * rsqrtf(var + 1e-5f);
    float sh = beta[co] - mean * sc;

    int i4 = blockIdx.x * 256 + tid;
    float4 v = ((const float4*)g_y)[i4];
    v.x = fmaxf(fmaf(v.x, sc, sh), 0.f);
    v.y = fmaxf(fmaf(v.y, sc, sh), 0.f);
    v.z = fmaxf(fmaf(v.z, sc, sh), 0.f);
    v.w = fmaxf(fmaf(v.w, sc, sh), 0.f);
    ((float4*)out)[i4] = v;
}

// ---------------------------------------------------------------------------
extern "C" void kernel_launch(void* const* d_in, const int* in_sizes, int n_in,
                              void* d_out, int out_size) {
    const float* x      = (const float*)d_in[0];
    const float* ind    = (const float*)d_in[1];
    const float* conv_w = (const float*)d_in[2];
    const float* conv_b = (const float*)d_in[3];
    const float* gamma  = (const float*)d_in[4];
    const float* beta   = (const float*)d_in[5];
    float* out = (float*)d_out;

    cudaFuncSetAttribute(gemm_half<1>, cudaFuncAttributeMaxDynamicSharedMemorySize, SMEM_DYN);
    cudaFuncSetAttribute(gemm_half<2>, cudaFuncAttributeMaxDynamicSharedMemorySize, SMEM_DYN);

    tsplit_deg_kernel<<<dim3(16, 16, BATCH), 256>>>(ind);
    combo_kernel<<<2468, 256>>>(conv_w);
    xs_half_kernel<<<8192, 256>>>(x);
    gemm_half<1><<<dim3(8, 2, BATCH), 256, SMEM_DYN>>>(nullptr);
    gemm_half<2><<<dim3(8, 2, BATCH), 256, SMEM_DYN>>>(conv_b);
    apply_kernel<<<2048, 256>>>(out, gamma, beta);
}

// round 11
// speedup vs baseline: 5.3726x; 1.0003x over previous
#include <cuda_runtime.h>
#include <cuda_fp16.h>
#include <math.h>
#include <stdint.h>

// ---------------------------------------------------------------------------
// GCN: out = relu(BN(conv3x3( D^-1/2 (A+I) D^-1/2 x ))), A = ind^T per batch
// b=8, c=256, n=1024 (32x32).
// R11: full-chunk fragment preload (24 independent ldsm, then 64 mma) to hide
// ldmatrix latency. Replaces the R9/R10 ping-pong formulation (which failed
// infra twice). All else identical to the passing R8 (92.2us).
// ---------------------------------------------------------------------------

#define BATCH 8
#define C     256
#define NPOS  1024
#define PADN  1156       // 34*34 zero-padded spatial
#define K2    2304       // 9*256 conv reduction

// ------------------------- device scratch ----------------------------------
__device__ __align__(16) float g_part[BATCH*NPOS*16];    // [b][i][jt] coalesced
__device__ __align__(16) float g_d[BATCH*NPOS];
__device__ __align__(16) __half g_iT[BATCH*NPOS*NPOS];   // (A+I)[i][j] fp16
__device__ __align__(16) __half g_xs[BATCH*C*NPOS];      // x*d[j], [c][j]
__device__ __align__(16) __half g_ip[BATCH*PADN*C];      // inter_pad [ppos][ci]
__device__ __align__(16) __half g_w2[C*K2];              // [co][tap*256+ci]
__device__ __align__(16) float g_y[BATCH*C*NPOS];        // conv out [b][co][pos]
__device__ __align__(16) float g_ps[C*64], g_pq[C*64];   // [co][slot]

// ------------------------- ptx helpers -------------------------------------
__device__ __forceinline__ uint32_t smem_u32(const void* p) {
    uint32_t a;
    asm("{ .reg .u64 t; cvta.to.shared.u64 t, %1; cvt.u32.u64 %0, t; }" : "=r"(a) : "l"(p));
    return a;
}
__device__ __forceinline__ void cp16(uint32_t dst, const void* src) {
    asm volatile("cp.async.cg.shared.global [%0], [%1], 16;" :: "r"(dst), "l"(src));
}
#define CP_COMMIT() asm volatile("cp.async.commit_group;" ::: "memory")
#define CP_WAIT(n)  asm volatile("cp.async.wait_group %0;" :: "n"(n) : "memory")

__device__ __forceinline__ void ldsm4(uint32_t* d, uint32_t addr) {
    asm volatile("ldmatrix.sync.aligned.m8n8.x4.shared.b16 {%0,%1,%2,%3}, [%4];"
        : "=r"(d[0]), "=r"(d[1]), "=r"(d[2]), "=r"(d[3]) : "r"(addr));
}
__device__ __forceinline__ void mma16816h(float* c, const uint32_t* a, const uint32_t* b) {
    asm volatile("mma.sync.aligned.m16n8k16.row.col.f32.f16.f16.f32 "
        "{%0,%1,%2,%3}, {%4,%5,%6,%7}, {%8,%9}, {%0,%1,%2,%3};"
        : "+f"(c[0]), "+f"(c[1]), "+f"(c[2]), "+f"(c[3])
        : "r"(a[0]), "r"(a[1]), "r"(a[2]), "r"(a[3]), "r"(b[0]), "r"(b[1]));
}

// ------------------------- prep kernels ------------------------------------
// 64x64 tile transpose ind -> fp16 (A+I); fused degree partials (pre-identity).
__global__ void __launch_bounds__(256) tsplit_deg_kernel(const float* __restrict__ ind) {
    __shared__ float t[64][65];
    int b = blockIdx.z;
    int i0 = blockIdx.x * 64, j0 = blockIdx.y * 64;
    int tid = threadIdx.x;

    {   // load 64 rows (j) x 64 cols (i), float4
        int r = tid >> 2, q = tid & 3;
        const float* src = ind + ((size_t)(b * NPOS + j0 + r)) * NPOS + i0;
        #pragma unroll
        for (int k = 0; k < 4; ++k) {
            float4 v = *(const float4*)(src + q * 4 + k * 16);
            t[r][q * 4 + k * 16]     = v.x;
            t[r][q * 4 + k * 16 + 1] = v.y;
            t[r][q * 4 + k * 16 + 2] = v.z;
            t[r][q * 4 + k * 16 + 3] = v.w;
        }
    }
    __syncthreads();

    int jh = tid & 31;                 // lane: half2 j index
    int wi = tid >> 5;                 // warp -> i row group
    #pragma unroll
    for (int iter = 0; iter < 8; ++iter) {
        int il = wi + iter * 8;
        int i = i0 + il;
        float r0 = t[2 * jh][il];
        float r1 = t[2 * jh + 1][il];
        float s = r0 + r1;             // degree BEFORE identity
        float v0 = r0 + ((i == j0 + 2 * jh)     ? 1.f : 0.f);
        float v1 = r1 + ((i == j0 + 2 * jh + 1) ? 1.f : 0.f);
        *(__half2*)(g_iT + ((size_t)(b * NPOS + i)) * NPOS + j0 + 2 * jh) =
            __floats2half2_rn(v0, v1);
        #pragma unroll
        for (int off = 16; off > 0; off >>= 1)
            s += __shfl_xor_sync(0xffffffffu, s, off);
        if (jh == 0)
            g_part[((size_t)(b * NPOS + i)) * 16 + blockIdx.y] = s;
    }
}

// combo: [0,2304) w->fp16 relayout | [2304,2436) pad border | [2436,2468) deg
__global__ void combo_kernel(const float* __restrict__ w) {
    int blk = blockIdx.x, tid = threadIdx.x;
    if (blk < 2304) {
        int o = blk * 256 + tid;              // < 256*2304
        int co = o / K2;
        int r = o - co * K2;
        int tap = r >> 8, ci = r & 255;
        g_w2[o] = __float2half(w[(size_t)(co * C + ci) * 9 + tap]);
    } else if (blk < 2436) {
        int k = blk - 2304;                   // border row 0..131
        int pp;
        if (k < 34)      pp = k;                              // top row
        else if (k < 68) pp = 33 * 34 + (k - 34);             // bottom row
        else {
            int m = k - 68;
            pp = (1 + (m >> 1)) * 34 + ((m & 1) ? 33 : 0);    // side cols
        }
        int b = tid >> 5, u = tid & 31;       // 8 batches x 32 uint4 = 256B row
        ((uint4*)(g_ip + ((size_t)(b * PADN + pp)) * C))[u] = make_uint4(0, 0, 0, 0);
    } else {
        int gi = (blk - 2436) * 256 + tid;    // (b,i) 0..8191
        const float4* p = (const float4*)(g_part + (size_t)gi * 16);
        float s = 0.f;
        #pragma unroll
        for (int k = 0; k < 4; ++k) {
            float4 v = p[k];
            s += (v.x + v.y) + (v.z + v.w);
        }
        g_d[gi] = sqrtf(1.0f / (s + 1e-8f));
    }
}

// xs[b][c][j] = fp16( x[b][c][j] * d[b][j] )
__global__ void xs_half_kernel(const float* __restrict__ x) {
    size_t idx = (size_t)blockIdx.x * 256 + threadIdx.x;
    int j = (int)(idx & (NPOS - 1));
    int b = (int)(idx >> 18);
    g_xs[idx] = __float2half(x[idx] * g_d[b * NPOS + j]);
}

// ------------------------- fp16 mma GEMM ------------------------------------
// MODE 1: D[pos 128][c 128]  = iT (A) . xs (B),             K=1024 (16 chunks)
// MODE 2: D[pos 128][co 128] = inter_pad shifted (A) . w2,  K=2304 (36 chunks)
// Stage = A|B, each 128x64 fp16 (16KB) -> 32KB/stage, 4-stage ring = 128KB.
static constexpr int SMEM_DYN = 4 * 32768;

template<int MODE>
__global__ void __launch_bounds__(256, 1) gemm_half(const float* __restrict__ conv_b) {
    extern __shared__ char smem[];
    uint32_t sb = smem_u32(smem);
    const int tid = threadIdx.x;
    const int pos0 = blockIdx.x * 128, n0 = blockIdx.y * 128, b = blockIdx.z;
    constexpr int CHUNKS = (MODE == 1) ? 16 : 36;

    auto stage = [&](int c, int p) {
        uint32_t base = sb + p * 32768;
        #pragma unroll
        for (int it = 0; it < 4; ++it) {
            int u = it * 256 + tid;           // 1024 16B-units per tile
            int r = u >> 3, g = u & 7;
            uint32_t sw = (uint32_t)(r * 128 + ((g ^ (r & 7)) * 16));
            const __half *pa, *pb;
            if (MODE == 1) {
                pa = g_iT + ((size_t)(b * NPOS + pos0 + r)) * NPOS + c * 64 + g * 8;
                pb = g_xs + ((size_t)(b * C + n0 + r)) * NPOS + c * 64 + g * 8;
            } else {
                int tap = c >> 2, ci0 = (c & 3) * 64;
                int pos = pos0 + r;
                int pp = ((pos >> 5) + 1) * 34 + (pos & 31) + 1
                         + (tap / 3 - 1) * 34 + (tap % 3 - 1);
                pa = g_ip + ((size_t)(b * PADN + pp)) * C + ci0 + g * 8;
                pb = g_w2 + ((size_t)(n0 + r)) * K2 + c * 64 + g * 8;
            }
            cp16(base + sw, pa);
            cp16(base + 16384 + sw, pb);
        }
    };

    const int l = tid & 31, w = tid >> 5;
    const int wm = w >> 2, wn = w & 3;             // 2 x 4 warp grid
    const int mbase = wm * 64, nbase = wn * 32;
    const int lr = l & 15;
    const uint32_t arow = (uint32_t)((mbase + lr) * 128);
    const uint32_t brow = (uint32_t)((nbase + lr) * 128);
    uint32_t u16[4];
    #pragma unroll
    for (int kk = 0; kk < 4; ++kk)
        u16[kk] = (uint32_t)(((kk * 2 + (l >> 4)) ^ (l & 7)) * 16);

    float acc[4][4][4];
    #pragma unroll
    for (int i = 0; i < 4; ++i)
        #pragma unroll
        for (int j = 0; j < 4; ++j)
            #pragma unroll
            for (int e = 0; e < 4; ++e) acc[i][j][e] = 0.f;

    stage(0, 0); CP_COMMIT();
    stage(1, 1); CP_COMMIT();
    stage(2, 2); CP_COMMIT();

    for (int c = 0; c < CHUNKS; ++c) {
        CP_WAIT(2);          // chunk c landed
        __syncthreads();     // all warps finished compute(c-1) -> its buffer free
        if (c + 3 < CHUNKS) { stage(c + 3, (c + 3) & 3); CP_COMMIT(); }
        uint32_t bb = sb + (c & 3) * 32768;

        // ---- full-chunk fragment preload: 24 independent ldsm ----
        uint32_t ah[4][4][4], bh[4][2][4];     // [kk][mi|nb][frag]
        #pragma unroll
        for (int kk = 0; kk < 4; ++kk) {
            #pragma unroll
            for (int mi = 0; mi < 4; ++mi)
                ldsm4(ah[kk][mi], bb + arow + mi * 2048 + u16[kk]);
            #pragma unroll
            for (int nb = 0; nb < 2; ++nb)
                ldsm4(bh[kk][nb], bb + 16384 + brow + nb * 2048 + u16[kk]);
        }
        // ---- 64 mma, all operands resident ----
        #pragma unroll
        for (int kk = 0; kk < 4; ++kk)
            #pragma unroll
            for (int mi = 0; mi < 4; ++mi)
                #pragma unroll
                for (int nj = 0; nj < 4; ++nj) {
                    int nb = nj >> 1, s = nj & 1;
                    uint32_t fh[2] = { bh[kk][nb][s], bh[kk][nb][s + 2] };
                    mma16816h(acc[mi][nj], ah[kk][mi], fh);
                }
    }
    __syncthreads();          // ring smem free for epilogue reuse

    // ---------------- epilogue ----------------
    int qr = l >> 2, qc = (l & 3) * 2;
    if (MODE == 1) {
        // stage fp16 tile [pos][ci] in smem, then coalesced 256B row writes
        __half* ips = (__half*)smem;               // [128][136]
        #pragma unroll
        for (int mi = 0; mi < 4; ++mi)
            #pragma unroll
            for (int half = 0; half < 2; ++half) {
                int pl = mbase + mi * 16 + qr + half * 8;
                float di = g_d[b * NPOS + pos0 + pl];
                #pragma unroll
                for (int nj = 0; nj < 4; ++nj) {
                    *(__half2*)(ips + pl * 136 + nbase + nj * 8 + qc) =
                        __floats2half2_rn(di * acc[mi][nj][half * 2],
                                          di * acc[mi][nj][half * 2 + 1]);
                }
            }
        __syncthreads();
        int row = tid >> 1, part = tid & 1;
        int pos = pos0 + row;
        int pp = ((pos >> 5) + 1) * 34 + (pos & 31) + 1;
        uint4* dst = (uint4*)(g_ip + ((size_t)(b * PADN + pp)) * C + n0) + part * 8;
        const uint4* srcp = (const uint4*)(ips + row * 136) + part * 8;
        #pragma unroll
        for (int k = 0; k < 8; ++k) dst[k] = srcp[k];
    } else {
        // stage fp32 tile transposed [co][pos] in smem; stream rows + BN partials
        float* ys = (float*)smem;                  // [128][132]
        #pragma unroll
        for (int mi = 0; mi < 4; ++mi)
            #pragma unroll
            for (int half = 0; half < 2; ++half) {
                int pl = mbase + mi * 16 + qr + half * 8;
                #pragma unroll
                for (int nj = 0; nj < 4; ++nj) {
                    int cl = nbase + nj * 8 + qc;
                    ys[cl * 132 + pl]       = acc[mi][nj][half * 2]     + conv_b[n0 + cl];
                    ys[(cl + 1) * 132 + pl] = acc[mi][nj][half * 2 + 1] + conv_b[n0 + cl + 1];
                }
            }
        __syncthreads();
        int cl = tid >> 1, part = tid & 1;
        const float4* rowp = (const float4*)(ys + cl * 132 + part * 64);
        float4* dst = (float4*)(g_y + ((size_t)(b * C + n0 + cl)) * NPOS + pos0 + part * 64);
        float s = 0.f, q = 0.f;
        #pragma unroll
        for (int k = 0; k < 16; ++k) {
            float4 v = rowp[k];
            s += (v.x + v.y) + (v.z + v.w);
            q += (v.x * v.x + v.y * v.y) + (v.z * v.z + v.w * v.w);
            dst[k] = v;
        }
        s += __shfl_xor_sync(0xffffffffu, s, 1);
        q += __shfl_xor_sync(0xffffffffu, q, 1);
        if (!part) {
            int slot = blockIdx.x * 8 + blockIdx.z;     // 0..63
            g_ps[(n0 + cl) * 64 + slot] = s;
            g_pq[(n0 + cl) * 64 + slot] = q;
        }
    }
}

// ------------------------- fused BN stats + apply ---------------------------
// one block = one (b,co) row of g_y (1024 floats = 256 float4)
__global__ void apply_kernel(float* __restrict__ out,
                             const float* __restrict__ gamma,
                             const float* __restrict__ beta) {
    __shared__ float sps[64], spq[64];
    int tid = threadIdx.x;
    int co = blockIdx.x & (C - 1);
    if (tid < 64)       sps[tid] = g_ps[co * 64 + tid];
    else if (tid < 128) spq[tid - 64] = g_pq[co * 64 + tid - 64];
    __syncthreads();
    float s = 0.f, q = 0.f;
    #pragma unroll
    for (int k = 0; k < 64; ++k) { s += sps[k]; q += spq[k]; }
    float mean = s * (1.0f / 8192.0f);
    float var  = q * (1.0f / 8192.0f) - mean * mean;
    float sc = gamma[co] * rsqrtf(var + 1e-5f);
    float sh = beta[co] - mean * sc;

    int i4 = blockIdx.x * 256 + tid;
    float4 v = ((const float4*)g_y)[i4];
    v.x = fmaxf(fmaf(v.x, sc, sh), 0.f);
    v.y = fmaxf(fmaf(v.y, sc, sh), 0.f);
    v.z = fmaxf(fmaf(v.z, sc, sh), 0.f);
    v.w = fmaxf(fmaf(v.w, sc, sh), 0.f);
    ((float4*)out)[i4] = v;
}

// ---------------------------------------------------------------------------
extern "C" void kernel_launch(void* const* d_in, const int* in_sizes, int n_in,
                              void* d_out, int out_size) {
    const float* x      = (const float*)d_in[0];
    const float* ind    = (const float*)d_in[1];
    const float* conv_w = (const float*)d_in[2];
    const float* conv_b = (const float*)d_in[3];
    const float* gamma  = (const float*)d_in[4];
    const float* beta   = (const float*)d_in[5];
    float* out = (float*)d_out;

    cudaFuncSetAttribute(gemm_half<1>, cudaFuncAttributeMaxDynamicSharedMemorySize, SMEM_DYN);
    cudaFuncSetAttribute(gemm_half<2>, cudaFuncAttributeMaxDynamicSharedMemorySize, SMEM_DYN);

    tsplit_deg_kernel<<<dim3(16, 16, BATCH), 256>>>(ind);
    combo_kernel<<<2468, 256>>>(conv_w);
    xs_half_kernel<<<8192, 256>>>(x);
    gemm_half<1><<<dim3(8, 2, BATCH), 256, SMEM_DYN>>>(nullptr);
    gemm_half<2><<<dim3(8, 2, BATCH), 256, SMEM_DYN>>>(conv_b);
    apply_kernel<<<2048, 256>>>(out, gamma, beta);
}